// round 2
// baseline (speedup 1.0000x reference)
#include <cuda_runtime.h>

#define T_STEPS 512
#define IN_F 5
#define HDIM 7

// sigmoid / tanh via EX2 + fast-rcp: ~1e-6 accuracy, 2 MUFU + ~3 FMA each.
__device__ __forceinline__ float sigf(float a) {
    return __fdividef(1.0f, 1.0f + __expf(-a));
}
__device__ __forceinline__ float tanhf_fast(float a) {
    return __fdividef(2.0f, 1.0f + __expf(-2.0f * a)) - 1.0f;
}

// 4 lanes per batch; lane L owns hidden units {2L, 2L+1} (unit 7 is a zero-weight dummy).
__global__ void __launch_bounds__(64) gru_kernel(
    const float* __restrict__ x,
    const float* __restrict__ W_ih, const float* __restrict__ W_hh,
    const float* __restrict__ b_ih, const float* __restrict__ b_hh,
    const float* __restrict__ W_h0,
    const float* __restrict__ W_m, const float* __restrict__ b_m,
    const float* __restrict__ W_r, const float* __restrict__ b_r,
    float* __restrict__ out, int B)
{
    int tid = blockIdx.x * blockDim.x + threadIdx.x;
    int b = tid >> 2;
    int L = tid & 3;
    if (b >= B) return;

    float* out_m = out;                                   // [B, T, 3]
    float* out_r = out + (size_t)B * T_STEPS * 3;         // [B, T, 1]
    float* out_h = out + (size_t)B * T_STEPS * 4;         // [1, B, H]

    // Per-lane weights in registers (no per-step LDS/LDC on the hot path).
    float wir[2][IN_F], wiz[2][IN_F], win[2][IN_F];
    float whr[2][HDIM], whz[2][HDIM], whn[2][HDIM];
    float br[2], bz[2], bxn[2], bhn[2];
    float wm0[2], wm1[2], wm2[2], wrr[2];
    float h[2];

#pragma unroll
    for (int s = 0; s < 2; s++) {
        int u = 2 * L + s;
        bool v = (u < HDIM);
        int ur = u, uz = HDIM + u, un = 2 * HDIM + u;
#pragma unroll
        for (int i = 0; i < IN_F; i++) {
            wir[s][i] = v ? W_ih[ur * IN_F + i] : 0.f;
            wiz[s][i] = v ? W_ih[uz * IN_F + i] : 0.f;
            win[s][i] = v ? W_ih[un * IN_F + i] : 0.f;
        }
#pragma unroll
        for (int k = 0; k < HDIM; k++) {
            whr[s][k] = v ? W_hh[ur * HDIM + k] : 0.f;
            whz[s][k] = v ? W_hh[uz * HDIM + k] : 0.f;
            whn[s][k] = v ? W_hh[un * HDIM + k] : 0.f;
        }
        br[s]  = v ? (b_ih[ur] + b_hh[ur]) : 0.f;
        bz[s]  = v ? (b_ih[uz] + b_hh[uz]) : 0.f;
        bxn[s] = v ? b_ih[un] : 0.f;
        bhn[s] = v ? b_hh[un] : 0.f;
        wm0[s] = v ? W_m[0 * HDIM + u] : 0.f;
        wm1[s] = v ? W_m[1 * HDIM + u] : 0.f;
        wm2[s] = v ? W_m[2 * HDIM + u] : 0.f;
        wrr[s] = v ? W_r[u] : 0.f;
        h[s]   = v ? W_h0[u] : 0.f;   // h0 = broadcast of W_h0 column
    }
    float ob = (L < 3) ? b_m[L] : b_r[0];

    const float* xb = x + (size_t)b * T_STEPS * IN_F;
    float* om  = out_m + (size_t)b * T_STEPS * 3;
    float* orr = out_r + (size_t)b * T_STEPS;

    for (int t = 0; t < T_STEPS; t++) {
        float xv[IN_F];
#pragma unroll
        for (int i = 0; i < IN_F; i++) xv[i] = __ldg(xb + t * IN_F + i);

        // All-gather the 7 live h values across the 4-lane group.
        float hall[8];
#pragma unroll
        for (int q = 0; q < 4; q++) {
            hall[2 * q]     = __shfl_sync(0xffffffffu, h[0], q, 4);
            hall[2 * q + 1] = __shfl_sync(0xffffffffu, h[1], q, 4);
        }

#pragma unroll
        for (int s = 0; s < 2; s++) {
            float Ar = br[s], Az = bz[s], Axn = bxn[s], Ahn = bhn[s];
#pragma unroll
            for (int i = 0; i < IN_F; i++) {
                Ar  = fmaf(wir[s][i], xv[i], Ar);
                Az  = fmaf(wiz[s][i], xv[i], Az);
                Axn = fmaf(win[s][i], xv[i], Axn);
            }
#pragma unroll
            for (int k = 0; k < HDIM; k++) {
                Ar  = fmaf(whr[s][k], hall[k], Ar);
                Az  = fmaf(whz[s][k], hall[k], Az);
                Ahn = fmaf(whn[s][k], hall[k], Ahn);
            }
            float r = sigf(Ar);
            float z = sigf(Az);
            float n = tanhf_fast(fmaf(r, Ahn, Axn));
            // (1-z)*n + z*h = n + z*(h - n)
            h[s] = fmaf(z, h[s] - n, n);
        }

        // Output heads: per-lane partials + butterfly reduce over the 4-lane group.
        float p0 = fmaf(wm0[0], h[0], wm0[1] * h[1]);
        float p1 = fmaf(wm1[0], h[0], wm1[1] * h[1]);
        float p2 = fmaf(wm2[0], h[0], wm2[1] * h[1]);
        float p3 = fmaf(wrr[0], h[0], wrr[1] * h[1]);
#pragma unroll
        for (int d = 1; d < 4; d <<= 1) {
            p0 += __shfl_xor_sync(0xffffffffu, p0, d, 4);
            p1 += __shfl_xor_sync(0xffffffffu, p1, d, 4);
            p2 += __shfl_xor_sync(0xffffffffu, p2, d, 4);
            p3 += __shfl_xor_sync(0xffffffffu, p3, d, 4);
        }
        float val = (L == 0) ? p0 : (L == 1) ? p1 : (L == 2) ? p2 : p3;
        val += ob;
        if (L < 3) om[t * 3 + L] = val;
        else       orr[t] = val;
    }

#pragma unroll
    for (int s = 0; s < 2; s++) {
        int u = 2 * L + s;
        if (u < HDIM) out_h[(size_t)b * HDIM + u] = h[s];
    }
}

extern "C" void kernel_launch(void* const* d_in, const int* in_sizes, int n_in,
                              void* d_out, int out_size) {
    // metadata order: x, batch_size, W_ih, W_hh, b_ih, b_hh, W_h0, W_m, b_m, W_r, b_r
    const float* x    = (const float*)d_in[0];
    const float* W_ih = (const float*)d_in[2];
    const float* W_hh = (const float*)d_in[3];
    const float* b_ih = (const float*)d_in[4];
    const float* b_hh = (const float*)d_in[5];
    const float* W_h0 = (const float*)d_in[6];
    const float* W_m  = (const float*)d_in[7];
    const float* b_m  = (const float*)d_in[8];
    const float* W_r  = (const float*)d_in[9];
    const float* b_r  = (const float*)d_in[10];

    int B = in_sizes[0] / (T_STEPS * IN_F);   // 8192
    int threads = B * 4;
    int block = 64;
    int grid = (threads + block - 1) / block;

    gru_kernel<<<grid, block>>>(x, W_ih, W_hh, b_ih, b_hh, W_h0,
                                W_m, b_m, W_r, b_r, (float*)d_out, B);
}

// round 3
// speedup vs baseline: 1.9160x; 1.9160x over previous
#include <cuda_runtime.h>

#define T_STEPS 512
#define IN_F 5
#define HDIM 7

__device__ __forceinline__ float tanh_ap(float a) {
    float r; asm("tanh.approx.f32 %0, %1;" : "=f"(r) : "f"(a)); return r;
}
__device__ __forceinline__ float sig_ap(float a) {
    return fmaf(0.5f, tanh_ap(0.5f * a), 0.5f);
}

// 4 lanes per batch; lane L owns hidden units {2L, 2L+1} (unit 7 = zero-weight dummy).
__global__ void __launch_bounds__(64) gru_kernel(
    const float* __restrict__ x,
    const float* __restrict__ W_ih, const float* __restrict__ W_hh,
    const float* __restrict__ b_ih, const float* __restrict__ b_hh,
    const float* __restrict__ W_h0,
    const float* __restrict__ W_m, const float* __restrict__ b_m,
    const float* __restrict__ W_r, const float* __restrict__ b_r,
    float* __restrict__ out, int B)
{
    int tid = blockIdx.x * blockDim.x + threadIdx.x;
    int b = tid >> 2;
    int L = tid & 3;
    if (b >= B) return;

    float* out_m = out;                             // [B, T, 3]
    float* out_r = out + (size_t)B * T_STEPS * 3;   // [B, T, 1]
    float* out_h = out + (size_t)B * T_STEPS * 4;   // [1, B, H]

    // ---- per-lane weights in registers ----
    float wir[2][IN_F], wiz[2][IN_F], win[2][IN_F];
    float whr[2][HDIM], whz[2][HDIM], whn[2][HDIM];
    float br[2], bz[2], bxn[2], bhn[2];
    float h[2];

#pragma unroll
    for (int s = 0; s < 2; s++) {
        int u = 2 * L + s;
        bool v = (u < HDIM);
        int ur = u, uz = HDIM + u, un = 2 * HDIM + u;
#pragma unroll
        for (int i = 0; i < IN_F; i++) {
            wir[s][i] = v ? W_ih[ur * IN_F + i] : 0.f;
            wiz[s][i] = v ? W_ih[uz * IN_F + i] : 0.f;
            win[s][i] = v ? W_ih[un * IN_F + i] : 0.f;
        }
#pragma unroll
        for (int k = 0; k < HDIM; k++) {
            whr[s][k] = v ? W_hh[ur * HDIM + k] : 0.f;
            whz[s][k] = v ? W_hh[uz * HDIM + k] : 0.f;
            whn[s][k] = v ? W_hh[un * HDIM + k] : 0.f;
        }
        br[s]  = v ? (b_ih[ur] + b_hh[ur]) : 0.f;
        bz[s]  = v ? (b_ih[uz] + b_hh[uz]) : 0.f;
        bxn[s] = v ? b_ih[un] : 0.f;
        bhn[s] = v ? b_hh[un] : 0.f;
        h[s]   = v ? W_h0[u] : 0.f;
    }
    // head row for this lane: lane 0..2 -> W_m rows, lane 3 -> W_r
    float wout[HDIM], ob;
#pragma unroll
    for (int k = 0; k < HDIM; k++)
        wout[k] = (L < 3) ? W_m[L * HDIM + k] : W_r[k];
    ob = (L < 3) ? b_m[L] : b_r[0];

    const float* xb = x + (size_t)b * T_STEPS * IN_F;
    float* om  = out_m + (size_t)b * T_STEPS * 3;
    float* orr = out_r + (size_t)b * T_STEPS;

    // ---- initial gather of h across the 4-lane group ----
    float hall[8];
#pragma unroll
    for (int q = 0; q < 4; q++) {
        hall[2 * q]     = __shfl_sync(0xffffffffu, h[0], q, 4);
        hall[2 * q + 1] = __shfl_sync(0xffffffffu, h[1], q, 4);
    }

    // ---- software pipeline: xa = input projection for current step;
    //      xv = raw x for next step (distance-2 prefetch via xnext) ----
    float xa_r[2], xa_z[2], xa_n[2];
    {
        float x0[IN_F];
#pragma unroll
        for (int i = 0; i < IN_F; i++) x0[i] = __ldg(xb + i);
#pragma unroll
        for (int s = 0; s < 2; s++) {
            float Ar = br[s], Az = bz[s], An = bxn[s];
#pragma unroll
            for (int i = 0; i < IN_F; i++) {
                Ar = fmaf(wir[s][i], x0[i], Ar);
                Az = fmaf(wiz[s][i], x0[i], Az);
                An = fmaf(win[s][i], x0[i], An);
            }
            xa_r[s] = Ar; xa_z[s] = Az; xa_n[s] = An;
        }
    }
    float xv[IN_F];
#pragma unroll
    for (int i = 0; i < IN_F; i++) xv[i] = __ldg(xb + IN_F + i);

#pragma unroll 2
    for (int t = 0; t < T_STEPS; t++) {
        // prefetch x[t+2] (clamped) — issued early, consumed next iteration
        int tld = (t + 2 < T_STEPS) ? (t + 2) : (T_STEPS - 1);
        float xnext[IN_F];
#pragma unroll
        for (int i = 0; i < IN_F; i++) xnext[i] = __ldg(xb + tld * IN_F + i);

        // ---- h-dependent gates (critical path) ----
#pragma unroll
        for (int s = 0; s < 2; s++) {
            // two-accumulator dot products over hall
            float Ar0 = xa_r[s], Ar1 = 0.f;
            float Az0 = xa_z[s], Az1 = 0.f;
            float An0 = bhn[s],  An1 = 0.f;
#pragma unroll
            for (int k = 0; k < HDIM; k += 2) {
                Ar0 = fmaf(whr[s][k], hall[k], Ar0);
                Az0 = fmaf(whz[s][k], hall[k], Az0);
                An0 = fmaf(whn[s][k], hall[k], An0);
                if (k + 1 < HDIM) {
                    Ar1 = fmaf(whr[s][k + 1], hall[k + 1], Ar1);
                    Az1 = fmaf(whz[s][k + 1], hall[k + 1], Az1);
                    An1 = fmaf(whn[s][k + 1], hall[k + 1], An1);
                }
            }
            float r = sig_ap(Ar0 + Ar1);
            float z = sig_ap(Az0 + Az1);
            float n = tanh_ap(fmaf(r, An0 + An1, xa_n[s]));
            h[s] = fmaf(z, h[s] - n, n);   // (1-z)n + z h
        }

        // ---- gather h(t) for the next step (also feeds the heads) ----
#pragma unroll
        for (int q = 0; q < 4; q++) {
            hall[2 * q]     = __shfl_sync(0xffffffffu, h[0], q, 4);
            hall[2 * q + 1] = __shfl_sync(0xffffffffu, h[1], q, 4);
        }

        // ---- heads: each lane computes its own output from hall ----
        float val = ob;
#pragma unroll
        for (int k = 0; k < HDIM; k++) val = fmaf(wout[k], hall[k], val);
        if (L < 3) om[t * 3 + L] = val;
        else       orr[t] = val;

        // ---- input projection for step t+1 (off critical path) ----
#pragma unroll
        for (int s = 0; s < 2; s++) {
            float Ar = br[s], Az = bz[s], An = bxn[s];
#pragma unroll
            for (int i = 0; i < IN_F; i++) {
                Ar = fmaf(wir[s][i], xv[i], Ar);
                Az = fmaf(wiz[s][i], xv[i], Az);
                An = fmaf(win[s][i], xv[i], An);
            }
            xa_r[s] = Ar; xa_z[s] = Az; xa_n[s] = An;
        }
#pragma unroll
        for (int i = 0; i < IN_F; i++) xv[i] = xnext[i];
    }

#pragma unroll
    for (int s = 0; s < 2; s++) {
        int u = 2 * L + s;
        if (u < HDIM) out_h[(size_t)b * HDIM + u] = h[s];
    }
}

extern "C" void kernel_launch(void* const* d_in, const int* in_sizes, int n_in,
                              void* d_out, int out_size) {
    const float* x    = (const float*)d_in[0];
    const float* W_ih = (const float*)d_in[2];
    const float* W_hh = (const float*)d_in[3];
    const float* b_ih = (const float*)d_in[4];
    const float* b_hh = (const float*)d_in[5];
    const float* W_h0 = (const float*)d_in[6];
    const float* W_m  = (const float*)d_in[7];
    const float* b_m  = (const float*)d_in[8];
    const float* W_r  = (const float*)d_in[9];
    const float* b_r  = (const float*)d_in[10];

    int B = in_sizes[0] / (T_STEPS * IN_F);
    int threads = B * 4;
    int block = 64;
    int grid = (threads + block - 1) / block;

    gru_kernel<<<grid, block>>>(x, W_ih, W_hh, b_ih, b_hh, W_h0,
                                W_m, b_m, W_r, b_r, (float*)d_out, B);
}

// round 5
// speedup vs baseline: 3.0246x; 1.5786x over previous
#include <cuda_runtime.h>

#define T_STEPS 512
#define IN_F 5
#define HDIM 7
#define TS 64                   // steps per smem tile
#define NTILE (T_STEPS / TS)    // 8
#define XROW (TS * IN_F + 12)   // 332 words: %32==12 (bank spread), %4==0 (float4)
#define OROW (TS * 4 + 4)       // 260 words: %32==4  (bank spread), %4==0

__device__ __forceinline__ float tanh_ap(float a) {
    float r; asm("tanh.approx.f32 %0, %1;" : "=f"(r) : "f"(a)); return r;
}
__device__ __forceinline__ float sig_ap(float a) {
    return fmaf(0.5f, tanh_ap(0.5f * a), 0.5f);
}

// 1 warp per CTA; warp = 8 batches x 4 lanes. Lane L owns hidden units {2L, 2L+1}
// (unit 7 is a zero-weight dummy; all loops over hall run k<7).
__global__ void __launch_bounds__(32) gru_kernel(
    const float* __restrict__ x,
    const float* __restrict__ W_ih, const float* __restrict__ W_hh,
    const float* __restrict__ b_ih, const float* __restrict__ b_hh,
    const float* __restrict__ W_h0,
    const float* __restrict__ W_m, const float* __restrict__ b_m,
    const float* __restrict__ W_r, const float* __restrict__ b_r,
    float* __restrict__ out, int B)
{
    __shared__ float xs[8 * XROW];   // staged x, per-batch row
    __shared__ float os[8 * OROW];   // staged outputs [tt*4 + head]

    int lane = threadIdx.x;
    int g = lane >> 2;
    int L = lane & 3;
    int b = blockIdx.x * 8 + g;
    if (blockIdx.x * 8 >= B) return;   // whole-warp exit only

    float* out_m = out;                             // [B, T, 3]
    float* out_r = out + (size_t)B * T_STEPS * 3;   // [B, T, 1]
    float* out_h = out + (size_t)B * T_STEPS * 4;   // [1, B, H]

    // ---- per-lane weights in registers ----
    float wir[2][IN_F], wiz[2][IN_F], win[2][IN_F];
    float whr[2][HDIM], whz[2][HDIM], whn[2][HDIM];
    float br[2], bz[2], bxn[2], bhn[2];
    float h[2];

#pragma unroll
    for (int s = 0; s < 2; s++) {
        int u = 2 * L + s;
        bool v = (u < HDIM);
        int ur = u, uz = HDIM + u, un = 2 * HDIM + u;
#pragma unroll
        for (int i = 0; i < IN_F; i++) {
            wir[s][i] = v ? W_ih[ur * IN_F + i] : 0.f;
            wiz[s][i] = v ? W_ih[uz * IN_F + i] : 0.f;
            win[s][i] = v ? W_ih[un * IN_F + i] : 0.f;
        }
#pragma unroll
        for (int k = 0; k < HDIM; k++) {
            whr[s][k] = v ? W_hh[ur * HDIM + k] : 0.f;
            whz[s][k] = v ? W_hh[uz * HDIM + k] : 0.f;
            whn[s][k] = v ? W_hh[un * HDIM + k] : 0.f;
        }
        br[s]  = v ? (b_ih[ur] + b_hh[ur]) : 0.f;
        bz[s]  = v ? (b_ih[uz] + b_hh[uz]) : 0.f;
        bxn[s] = v ? b_ih[un] : 0.f;
        bhn[s] = v ? b_hh[un] : 0.f;
        h[s]   = v ? W_h0[u] : 0.f;
    }
    float wout[HDIM], ob;
#pragma unroll
    for (int k = 0; k < HDIM; k++)
        wout[k] = (L < 3) ? W_m[L * HDIM + k] : W_r[k];
    ob = (L < 3) ? b_m[L] : b_r[0];

    const float* xb = x + (size_t)b * T_STEPS * IN_F;
    float* xrow = xs + g * XROW;
    float* orow = os + g * OROW;

    // initial gather of h0 (7 live values)
    float hall[HDIM];
#pragma unroll
    for (int q = 0; q < 4; q++) {
        hall[2 * q] = __shfl_sync(0xffffffffu, h[0], q, 4);
        if (2 * q + 1 < HDIM)
            hall[2 * q + 1] = __shfl_sync(0xffffffffu, h[1], q, 4);
    }

    for (int tile = 0; tile < NTILE; tile++) {
        int t0 = tile * TS;

        // ---- stage x tile: 8 batches x 320 floats, coalesced float4 ----
        __syncwarp();
        const float4* src = (const float4*)(xb + t0 * IN_F);
#pragma unroll
        for (int j = 0; j < (TS * IN_F) / 16; j++) {   // 20
            float4 v = src[L + 4 * j];
            *(float4*)(xrow + (L + 4 * j) * 4) = v;
        }
        __syncwarp();

        // ---- pipeline preamble: xa = proj(x[t0]); xvn = x[t0+1] ----
        float xa_r[2], xa_z[2], xa_n[2], xvn[IN_F];
        {
            float x0[IN_F];
#pragma unroll
            for (int i = 0; i < IN_F; i++) x0[i] = xrow[i];
#pragma unroll
            for (int s = 0; s < 2; s++) {
                float Ar = br[s], Az = bz[s], An = bxn[s];
#pragma unroll
                for (int i = 0; i < IN_F; i++) {
                    Ar = fmaf(wir[s][i], x0[i], Ar);
                    Az = fmaf(wiz[s][i], x0[i], Az);
                    An = fmaf(win[s][i], x0[i], An);
                }
                xa_r[s] = Ar; xa_z[s] = Az; xa_n[s] = An;
            }
#pragma unroll
            for (int i = 0; i < IN_F; i++) xvn[i] = xrow[IN_F + i];
        }

#pragma unroll 2
        for (int tt = 0; tt < TS; tt++) {
            // prefetch x[tt+2] from smem (clamped)
            int t2 = (tt + 2 < TS) ? (tt + 2) : (TS - 1);
            float xv2[IN_F];
#pragma unroll
            for (int i = 0; i < IN_F; i++) xv2[i] = xrow[t2 * IN_F + i];

            // ---- gates from xa(t) and hall(t-1) ----
#pragma unroll
            for (int s = 0; s < 2; s++) {
                float Ar0 = xa_r[s], Ar1 = 0.f;
                float Az0 = xa_z[s], Az1 = 0.f;
                float An0 = bhn[s],  An1 = 0.f;
#pragma unroll
                for (int k = 0; k < HDIM; k += 2) {
                    Ar0 = fmaf(whr[s][k], hall[k], Ar0);
                    Az0 = fmaf(whz[s][k], hall[k], Az0);
                    An0 = fmaf(whn[s][k], hall[k], An0);
                    if (k + 1 < HDIM) {
                        Ar1 = fmaf(whr[s][k + 1], hall[k + 1], Ar1);
                        Az1 = fmaf(whz[s][k + 1], hall[k + 1], Az1);
                        An1 = fmaf(whn[s][k + 1], hall[k + 1], An1);
                    }
                }
                float r = sig_ap(Ar0 + Ar1);
                float z = sig_ap(Az0 + Az1);
                float n = tanh_ap(fmaf(r, An0 + An1, xa_n[s]));
                h[s] = fmaf(z, h[s] - n, n);
            }

            // ---- gather hall(t) for next step + heads ----
#pragma unroll
            for (int q = 0; q < 4; q++) {
                hall[2 * q] = __shfl_sync(0xffffffffu, h[0], q, 4);
                if (2 * q + 1 < HDIM)
                    hall[2 * q + 1] = __shfl_sync(0xffffffffu, h[1], q, 4);
            }
            float val = ob;
#pragma unroll
            for (int k = 0; k < HDIM; k++) val = fmaf(wout[k], hall[k], val);
            orow[tt * 4 + L] = val;    // conflict-free: bank = 4g + L (+4tt)

            // ---- input projection for step t+1 (off critical path) ----
#pragma unroll
            for (int s = 0; s < 2; s++) {
                float Ar = br[s], Az = bz[s], An = bxn[s];
#pragma unroll
                for (int i = 0; i < IN_F; i++) {
                    Ar = fmaf(wir[s][i], xvn[i], Ar);
                    Az = fmaf(wiz[s][i], xvn[i], Az);
                    An = fmaf(win[s][i], xvn[i], An);
                }
                xa_r[s] = Ar; xa_z[s] = Az; xa_n[s] = An;
            }
#pragma unroll
            for (int i = 0; i < IN_F; i++) xvn[i] = xv2[i];
        }
        __syncwarp();

        // ---- flush out_m tile: 192 floats/batch as 12 float4 per lane ----
        float* omg = out_m + (size_t)b * T_STEPS * 3 + t0 * 3;
#pragma unroll
        for (int q = 0; q < 12; q++) {
            int p = (4 * q + L) * 4;
            float4 v;
            v.x = orow[((p + 0) / 3) * 4 + (p + 0) % 3];
            v.y = orow[((p + 1) / 3) * 4 + (p + 1) % 3];
            v.z = orow[((p + 2) / 3) * 4 + (p + 2) % 3];
            v.w = orow[((p + 3) / 3) * 4 + (p + 3) % 3];
            *(float4*)(omg + p) = v;
        }
        // ---- flush out_r tile: 64 floats/batch as 4 float4 per lane ----
        float* org = out_r + (size_t)b * T_STEPS + t0;
#pragma unroll
        for (int q = 0; q < 4; q++) {
            int p = (4 * q + L) * 4;
            float4 v;
            v.x = orow[(p + 0) * 4 + 3];
            v.y = orow[(p + 1) * 4 + 3];
            v.z = orow[(p + 2) * 4 + 3];
            v.w = orow[(p + 3) * 4 + 3];
            *(float4*)(org + p) = v;
        }
    }

#pragma unroll
    for (int s = 0; s < 2; s++) {
        int u = 2 * L + s;
        if (u < HDIM) out_h[(size_t)b * HDIM + u] = h[s];
    }
}

extern "C" void kernel_launch(void* const* d_in, const int* in_sizes, int n_in,
                              void* d_out, int out_size) {
    const float* x    = (const float*)d_in[0];
    const float* W_ih = (const float*)d_in[2];
    const float* W_hh = (const float*)d_in[3];
    const float* b_ih = (const float*)d_in[4];
    const float* b_hh = (const float*)d_in[5];
    const float* W_h0 = (const float*)d_in[6];
    const float* W_m  = (const float*)d_in[7];
    const float* b_m  = (const float*)d_in[8];
    const float* W_r  = (const float*)d_in[9];
    const float* b_r  = (const float*)d_in[10];

    int B = in_sizes[0] / (T_STEPS * IN_F);   // 8192
    int grid = (B + 7) / 8;                   // 8 batches per 1-warp CTA
    gru_kernel<<<grid, 32>>>(x, W_ih, W_hh, b_ih, b_hh, W_h0,
                             W_m, b_m, W_r, b_r, (float*)d_out, B);
}

// round 6
// speedup vs baseline: 3.2905x; 1.0879x over previous
#include <cuda_runtime.h>

#define T_STEPS 512
#define IN_F 5
#define HDIM 7
#define TS 64
#define NTILE (T_STEPS / TS)
#define XROW (TS * IN_F + 12)   // 332 words: bank spread, float4-aligned
#define OROW (TS * 4 + 4)       // 260 words

typedef unsigned long long u64;

__device__ __forceinline__ float tanh_ap(float a) {
    float r; asm("tanh.approx.f32 %0, %1;" : "=f"(r) : "f"(a)); return r;
}
// packed f32x2 helpers (sm_100+)
__device__ __forceinline__ u64 pk(float lo, float hi) {
    u64 r; asm("mov.b64 %0, {%1, %2};" : "=l"(r) : "f"(lo), "f"(hi)); return r;
}
__device__ __forceinline__ u64 pk1(float v) { return pk(v, v); }
__device__ __forceinline__ void up(u64 v, float& lo, float& hi) {
    asm("mov.b64 {%0, %1}, %2;" : "=f"(lo), "=f"(hi) : "l"(v));
}
__device__ __forceinline__ u64 f2(u64 a, u64 b, u64 c) {
    u64 d; asm("fma.rn.f32x2 %0, %1, %2, %3;" : "=l"(d) : "l"(a), "l"(b), "l"(c)); return d;
}
__device__ __forceinline__ u64 a2(u64 a, u64 b) {
    u64 d; asm("add.rn.f32x2 %0, %1, %2;" : "=l"(d) : "l"(a), "l"(b)); return d;
}

// 1 warp/CTA; warp = 8 batches x 4 lanes. Lane L owns units {2L, 2L+1} packed lo/hi
// (unit 7 = zero-weight dummy).
__global__ void __launch_bounds__(32) gru_kernel(
    const float* __restrict__ x,
    const float* __restrict__ W_ih, const float* __restrict__ W_hh,
    const float* __restrict__ b_ih, const float* __restrict__ b_hh,
    const float* __restrict__ W_h0,
    const float* __restrict__ W_m, const float* __restrict__ b_m,
    const float* __restrict__ W_r, const float* __restrict__ b_r,
    float* __restrict__ out, int B)
{
    __shared__ float xs[8 * XROW];
    __shared__ float os[8 * OROW];

    int lane = threadIdx.x;
    int g = lane >> 2;
    int L = lane & 3;
    int b = blockIdx.x * 8 + g;

    float* out_m = out;
    float* out_r = out + (size_t)B * T_STEPS * 3;
    float* out_h = out + (size_t)B * T_STEPS * 4;

    // ---- packed per-lane weights (lo = unit 2L, hi = unit 2L+1) ----
    u64 pwir[IN_F], pwiz[IN_F], pwin[IN_F];
    u64 pwhr[HDIM], pwhz[HDIM], pwhn[HDIM];
    u64 pbr, pbz, pbxn, pbhn;
    float h0s, h1s;   // h kept scalar (feeds shuffles / update)

    {
        int u0 = 2 * L, u1 = 2 * L + 1;
        bool v1 = (u1 < HDIM);
        int r0 = u0, z0 = HDIM + u0, n0 = 2 * HDIM + u0;
        int r1 = u1, z1 = HDIM + u1, n1 = 2 * HDIM + u1;
#pragma unroll
        for (int i = 0; i < IN_F; i++) {
            pwir[i] = pk(W_ih[r0 * IN_F + i], v1 ? W_ih[r1 * IN_F + i] : 0.f);
            pwiz[i] = pk(W_ih[z0 * IN_F + i], v1 ? W_ih[z1 * IN_F + i] : 0.f);
            pwin[i] = pk(W_ih[n0 * IN_F + i], v1 ? W_ih[n1 * IN_F + i] : 0.f);
        }
#pragma unroll
        for (int k = 0; k < HDIM; k++) {
            pwhr[k] = pk(W_hh[r0 * HDIM + k], v1 ? W_hh[r1 * HDIM + k] : 0.f);
            pwhz[k] = pk(W_hh[z0 * HDIM + k], v1 ? W_hh[z1 * HDIM + k] : 0.f);
            pwhn[k] = pk(W_hh[n0 * HDIM + k], v1 ? W_hh[n1 * HDIM + k] : 0.f);
        }
        pbr  = pk(b_ih[r0] + b_hh[r0], v1 ? (b_ih[r1] + b_hh[r1]) : 0.f);
        pbz  = pk(b_ih[z0] + b_hh[z0], v1 ? (b_ih[z1] + b_hh[z1]) : 0.f);
        pbxn = pk(b_ih[n0], v1 ? b_ih[n1] : 0.f);
        pbhn = pk(b_hh[n0], v1 ? b_hh[n1] : 0.f);
        h0s = W_h0[u0];
        h1s = v1 ? W_h0[u1] : 0.f;
    }
    float wout[HDIM], ob;
#pragma unroll
    for (int k = 0; k < HDIM; k++)
        wout[k] = (L < 3) ? W_m[L * HDIM + k] : W_r[k];
    ob = (L < 3) ? b_m[L] : b_r[0];

    const float* xb = x + (size_t)b * T_STEPS * IN_F;
    float* xrow = xs + g * XROW;
    float* orow = os + g * OROW;

    // initial gather of h0
    float hall[HDIM];
#pragma unroll
    for (int q = 0; q < 4; q++) {
        hall[2 * q] = __shfl_sync(0xffffffffu, h0s, q, 4);
        if (2 * q + 1 < HDIM)
            hall[2 * q + 1] = __shfl_sync(0xffffffffu, h1s, q, 4);
    }

    for (int tile = 0; tile < NTILE; tile++) {
        int t0 = tile * TS;

        // stage x tile (coalesced float4)
        __syncwarp();
        const float4* src = (const float4*)(xb + t0 * IN_F);
#pragma unroll
        for (int j = 0; j < (TS * IN_F) / 16; j++) {
            float4 v = src[L + 4 * j];
            *(float4*)(xrow + (L + 4 * j) * 4) = v;
        }
        __syncwarp();

        // preamble: packed projection of x[t0]; xvn = x[t0+1]
        u64 pxa_r, pxa_z, pxa_n;
        float xvn[IN_F];
        {
            u64 Ar = pbr, Az = pbz, An = pbxn;
#pragma unroll
            for (int i = 0; i < IN_F; i++) {
                u64 xi = pk1(xrow[i]);
                Ar = f2(pwir[i], xi, Ar);
                Az = f2(pwiz[i], xi, Az);
                An = f2(pwin[i], xi, An);
            }
            pxa_r = Ar; pxa_z = Az; pxa_n = An;
#pragma unroll
            for (int i = 0; i < IN_F; i++) xvn[i] = xrow[IN_F + i];
        }

#pragma unroll 2
        for (int tt = 0; tt < TS; tt++) {
            int t2 = (tt + 2 < TS) ? (tt + 2) : (TS - 1);
            float xv2[IN_F];
#pragma unroll
            for (int i = 0; i < IN_F; i++) xv2[i] = xrow[t2 * IN_F + i];

            // ---- packed gate dot-products over hall (2 accumulators) ----
            u64 ph[HDIM];
#pragma unroll
            for (int k = 0; k < HDIM; k++) ph[k] = pk1(hall[k]);

            u64 Ar0 = pxa_r, Ar1 = pk(0.f, 0.f);
            u64 Az0 = pxa_z, Az1 = pk(0.f, 0.f);
            u64 An0 = pbhn,  An1 = pk(0.f, 0.f);
#pragma unroll
            for (int k = 0; k < HDIM; k += 2) {
                Ar0 = f2(pwhr[k], ph[k], Ar0);
                Az0 = f2(pwhz[k], ph[k], Az0);
                An0 = f2(pwhn[k], ph[k], An0);
                if (k + 1 < HDIM) {
                    Ar1 = f2(pwhr[k + 1], ph[k + 1], Ar1);
                    Az1 = f2(pwhz[k + 1], ph[k + 1], Az1);
                    An1 = f2(pwhn[k + 1], ph[k + 1], An1);
                }
            }
            u64 pAr = a2(Ar0, Ar1);
            u64 pAz = a2(Az0, Az1);
            u64 pAn = a2(An0, An1);

            // ---- scalar transcendentals + h update per unit ----
            float ar0, ar1, az0, az1, an0, an1, xn0, xn1;
            up(pAr, ar0, ar1); up(pAz, az0, az1);
            up(pAn, an0, an1); up(pxa_n, xn0, xn1);

            float r0 = fmaf(0.5f, tanh_ap(0.5f * ar0), 0.5f);
            float r1 = fmaf(0.5f, tanh_ap(0.5f * ar1), 0.5f);
            float z0 = fmaf(0.5f, tanh_ap(0.5f * az0), 0.5f);
            float z1 = fmaf(0.5f, tanh_ap(0.5f * az1), 0.5f);
            float n0 = tanh_ap(fmaf(r0, an0, xn0));
            float n1 = tanh_ap(fmaf(r1, an1, xn1));
            h0s = fmaf(z0, h0s - n0, n0);
            h1s = fmaf(z1, h1s - n1, n1);

            // ---- gather h(t) + heads ----
#pragma unroll
            for (int q = 0; q < 4; q++) {
                hall[2 * q] = __shfl_sync(0xffffffffu, h0s, q, 4);
                if (2 * q + 1 < HDIM)
                    hall[2 * q + 1] = __shfl_sync(0xffffffffu, h1s, q, 4);
            }
            float val = ob;
#pragma unroll
            for (int k = 0; k < HDIM; k++) val = fmaf(wout[k], hall[k], val);
            orow[tt * 4 + L] = val;

            // ---- packed projection for step t+1 (off critical path) ----
            {
                u64 Ar = pbr, Az = pbz, An = pbxn;
#pragma unroll
                for (int i = 0; i < IN_F; i++) {
                    u64 xi = pk1(xvn[i]);
                    Ar = f2(pwir[i], xi, Ar);
                    Az = f2(pwiz[i], xi, Az);
                    An = f2(pwin[i], xi, An);
                }
                pxa_r = Ar; pxa_z = Az; pxa_n = An;
            }
#pragma unroll
            for (int i = 0; i < IN_F; i++) xvn[i] = xv2[i];
        }
        __syncwarp();

        // ---- flush out_m tile ----
        float* omg = out_m + (size_t)b * T_STEPS * 3 + t0 * 3;
#pragma unroll
        for (int q = 0; q < 12; q++) {
            int p = (4 * q + L) * 4;
            float4 v;
            v.x = orow[((p + 0) / 3) * 4 + (p + 0) % 3];
            v.y = orow[((p + 1) / 3) * 4 + (p + 1) % 3];
            v.z = orow[((p + 2) / 3) * 4 + (p + 2) % 3];
            v.w = orow[((p + 3) / 3) * 4 + (p + 3) % 3];
            *(float4*)(omg + p) = v;
        }
        // ---- flush out_r tile ----
        float* org = out_r + (size_t)b * T_STEPS + t0;
#pragma unroll
        for (int q = 0; q < 4; q++) {
            int p = (4 * q + L) * 4;
            float4 v;
            v.x = orow[(p + 0) * 4 + 3];
            v.y = orow[(p + 1) * 4 + 3];
            v.z = orow[(p + 2) * 4 + 3];
            v.w = orow[(p + 3) * 4 + 3];
            *(float4*)(org + p) = v;
        }
    }

    {
        int u0 = 2 * L, u1 = 2 * L + 1;
        out_h[(size_t)b * HDIM + u0] = h0s;
        if (u1 < HDIM) out_h[(size_t)b * HDIM + u1] = h1s;
    }
}

extern "C" void kernel_launch(void* const* d_in, const int* in_sizes, int n_in,
                              void* d_out, int out_size) {
    const float* x    = (const float*)d_in[0];
    const float* W_ih = (const float*)d_in[2];
    const float* W_hh = (const float*)d_in[3];
    const float* b_ih = (const float*)d_in[4];
    const float* b_hh = (const float*)d_in[5];
    const float* W_h0 = (const float*)d_in[6];
    const float* W_m  = (const float*)d_in[7];
    const float* b_m  = (const float*)d_in[8];
    const float* W_r  = (const float*)d_in[9];
    const float* b_r  = (const float*)d_in[10];

    int B = in_sizes[0] / (T_STEPS * IN_F);
    int grid = (B + 7) / 8;
    gru_kernel<<<grid, 32>>>(x, W_ih, W_hh, b_ih, b_hh, W_h0,
                             W_m, b_m, W_r, b_r, (float*)d_out, B);
}